// round 16
// baseline (speedup 1.0000x reference)
#include <cuda_runtime.h>
#include <cuda_bf16.h>

// LightplaneSplatter: splat N rays x 72 samples x 16 channels into a
// (1,128,128,128,16) grid with trilinear weights, masking OOB corners.
//
// R15: single persistent kernel, software global barrier, in-kernel overlap:
//   phase 1: all 148 blocks zero vertex planes z in [0, ZC+1)      (~4us)
//   phase 2: blocks < ZB zero planes [ZC+1, 128)  (DRAM-bound)
//            blocks >= ZB splat cells bz <= ZC-1  (LSU-bound)      (overlap)
//   phase 3: all blocks splat cells bz >= ZC                        (~74us)
// Grid = 148 blocks (1/SM, co-residency guaranteed: occupancy cap is 3
// blocks/SM at 576 threads), so the atomic-counter barrier cannot deadlock.
// Per-ray z-range prune (vz monotone in t) skips geometry for rays that
// never enter the lo slab.
//
// Inputs (metadata order):
//   d_in[0] directions  float32 [N,3]
//   d_in[1] origins     float32 [N,3]
//   d_in[2] near        float32 [N]
//   d_in[3] far         float32 [N]
//   d_in[4] encoding    float32 [N,16]
//   d_in[5] grid_idx    int32   [N]
// Output: float32 grid [1,128,128,128,16] flattened (33,554,432 elems).

#define GW 128
#define GH 128
#define GD 128
#define GC 16
#define NUM_SAMPLES 64
#define NUM_SAMPLES_INF 8
#define ST (NUM_SAMPLES + NUM_SAMPLES_INF)  // 72
#define DISPARITY_AT_INF 1e-4f

// Strides in floats
#define SXs (GC)            // 16
#define SYs (GW * GC)       // 2048
#define SZs (GH * GW * GC)  // 262144

#define NBLK 148   // one block per SM
#define NTHR 576   // 2 rays x 72 samples x 4 channel-quads
#define ZC   20    // lo cells: bz <= ZC-1 (touch planes z <= ZC)
#define ZB   36    // blocks 0..ZB-1 zero the hi planes in phase 2

__device__ int g_count = 0;
__device__ int g_gen   = 0;

__device__ __forceinline__ void gbar() {
    __syncthreads();
    if (threadIdx.x == 0) {
        __threadfence();
        volatile int* vgen = &g_gen;
        const int gen = *vgen;
        if (atomicAdd(&g_count, 1) == NBLK - 1) {
            g_count = 0;
            __threadfence();
            atomicExch(&g_gen, gen + 1);
        } else {
            while (*vgen == gen) { __nanosleep(64); }
        }
        __threadfence();
    }
    __syncthreads();
}

__device__ __forceinline__ void red_add_v4(float* p, float x, float y, float z, float w) {
    asm volatile("red.global.add.v4.f32 [%0], {%1, %2, %3, %4};"
                 :: "l"(p), "f"(x), "f"(y), "f"(z), "f"(w)
                 : "memory");
}

// Splat one (ray, sample, channel-quad); emits only cells with bz in [zlo, zhi].
__device__ __forceinline__ void splat_sample(
    int n, int si, int c4, int zlo, int zhi,
    const float* __restrict__ dirs, const float* __restrict__ orig,
    const float* __restrict__ nearv, const float* __restrict__ farv,
    const float* __restrict__ enc, const int* __restrict__ gidx,
    float* __restrict__ out)
{
    const float nr = nearv[n];
    const float fr = farv[n];

    float t;
    if (si < NUM_SAMPLES) {
        t = nr + (fr - nr) * (((float)si + 0.5f) * (1.0f / NUM_SAMPLES));
    } else {
        const float j    = (float)(si - NUM_SAMPLES + 1) * (1.0f / NUM_SAMPLES_INF);
        const float invf = 1.0f / fr;
        const float disp = invf + (DISPARITY_AT_INF - invf) * j;
        t = 1.0f / disp;
    }

    const float px = orig[n * 3 + 0] + t * dirs[n * 3 + 0];
    const float py = orig[n * 3 + 1] + t * dirs[n * 3 + 1];
    const float pz = orig[n * 3 + 2] + t * dirs[n * 3 + 2];

    const float vx = (px + 1.0f) * 0.5f * (float)(GW - 1);
    const float vy = (py + 1.0f) * 0.5f * (float)(GH - 1);
    const float vz = (pz + 1.0f) * 0.5f * (float)(GD - 1);

    const float bxf = floorf(vx);
    const float byf = floorf(vy);
    const float bzf = floorf(vz);

    // Written so NaN also fails -> skip.
    const bool maybe_in =
        (bxf >= -1.0f) && (bxf <= (float)(GW - 1)) &&
        (byf >= -1.0f) && (byf <= (float)(GH - 1)) &&
        (bzf >= -1.0f) && (bzf <= (float)(GD - 1));
    if (!maybe_in) return;

    const int bz = (int)bzf;
    if (bz < zlo || bz > zhi) return;   // other phase handles it

    const float fx = vx - bxf;
    const float fy = vy - byf;
    const float fz = vz - bzf;
    const int bx = (int)bxf;
    const int by = (int)byf;

    const float4 e = *reinterpret_cast<const float4*>(enc + n * GC + c4 * 4);
    const int   b = gidx[n];

    const float wx0 = 1.0f - fx, wx1 = fx;
    const float wy0 = 1.0f - fy, wy1 = fy;
    const float wz0 = 1.0f - fz, wz1 = fz;

    const bool x0 = (unsigned)bx       < GW;
    const bool x1 = (unsigned)(bx + 1) < GW;
    const bool y0 = (unsigned)by       < GH;
    const bool y1 = (unsigned)(by + 1) < GH;
    const bool z0 = (unsigned)bz       < GD;
    const bool z1 = (unsigned)(bz + 1) < GD;

    const long long basef =
        ((((long long)b * GD + bz) * GH + by) * GW + bx) * GC + c4 * 4;
    float* const pb = out + basef;

#pragma unroll
    for (int k = 0; k < 8; k++) {
        const int ddx = k & 1, ddy = (k >> 1) & 1, ddz = (k >> 2) & 1;
        const bool inb = (ddx ? x1 : x0) & (ddy ? y1 : y0) & (ddz ? z1 : z0);
        if (inb) {
            const float w = (ddx ? wx1 : wx0) * (ddy ? wy1 : wy0) * (ddz ? wz1 : wz0);
            red_add_v4(pb + (ddz * SZs + ddy * SYs + ddx * SXs),
                       w * e.x, w * e.y, w * e.z, w * e.w);
        }
    }
}

// Conservative per-ray test: can any sample's cell have bz in [zlo, zhi]?
// vz is monotone in t (up to rounding); slack 1.0 voxels absorbs fp noise.
__device__ __forceinline__ bool ray_touches_z(
    int n, int zlo, int zhi,
    const float* __restrict__ dirs, const float* __restrict__ orig,
    const float* __restrict__ nearv, const float* __restrict__ farv)
{
    const float dz_ = dirs[n * 3 + 2];
    const float oz_ = orig[n * 3 + 2];
    const float nr = nearv[n], fr = farv[n];
    const float t0 = nr + (fr - nr) * (0.5f / NUM_SAMPLES);
    const float t1 = 1.0f / DISPARITY_AT_INF;  // max sample depth
    const float va = (oz_ + t0 * dz_ + 1.0f) * 0.5f * (float)(GD - 1);
    const float vb = (oz_ + t1 * dz_ + 1.0f) * 0.5f * (float)(GD - 1);
    const float vmin = fminf(va, vb);
    const float vmax = fmaxf(va, vb);
    if (vmin > (float)(zhi + 1) + 1.0f) return false;  // all floors > zhi
    if (vmax < (float)zlo - 1.0f)       return false;  // all floors < zlo
    return true;
}

__global__ void __launch_bounds__(NTHR) fused_kernel(
    const float* __restrict__ dirs,
    const float* __restrict__ orig,
    const float* __restrict__ nearv,
    const float* __restrict__ farv,
    const float* __restrict__ enc,
    const int*   __restrict__ gidx,
    float* __restrict__ out,
    int N, long long out_floats)
{
    const int tid = threadIdx.x;
    const int bid = blockIdx.x;

    float4* const out4 = (float4*)out;
    const float4 z4 = make_float4(0.f, 0.f, 0.f, 0.f);
    const long long lo4  = (long long)(ZC + 1) * SZs / 4;  // planes [0, ZC+1)
    const long long all4 = out_floats / 4;

    // thread -> (ray-slot, sample, channel-quad)
    const int rp  = tid / 288;          // 0 or 1
    const int rem = tid - rp * 288;
    const int si  = rem >> 2;           // 0..71
    const int c4  = rem & 3;            // 0..3

    // ---- phase 1: zero lo planes ----
    for (long long i = (long long)bid * NTHR + tid; i < lo4;
         i += (long long)NBLK * NTHR)
        out4[i] = z4;
    gbar();

    // ---- phase 2: overlap hi zeroing with lo splat ----
    if (bid < ZB) {
        for (long long i = lo4 + (long long)bid * NTHR + tid; i < all4;
             i += (long long)ZB * NTHR)
            out4[i] = z4;
    } else {
        const int nb = NBLK - ZB;
        for (int r = (bid - ZB) * 2 + rp; r < N; r += nb * 2) {
            if (!ray_touches_z(r, -1, ZC - 1, dirs, orig, nearv, farv)) continue;
            splat_sample(r, si, c4, -1000000, ZC - 1,
                         dirs, orig, nearv, farv, enc, gidx, out);
        }
    }
    gbar();

    // ---- phase 3: splat hi cells ----
    for (int r = bid * 2 + rp; r < N; r += NBLK * 2) {
        if (!ray_touches_z(r, ZC, GD - 1, dirs, orig, nearv, farv)) continue;
        splat_sample(r, si, c4, ZC, 1000000,
                     dirs, orig, nearv, farv, enc, gidx, out);
    }
}

extern "C" void kernel_launch(void* const* d_in, const int* in_sizes, int n_in,
                              void* d_out, int out_size)
{
    const float* dirs  = (const float*)d_in[0];
    const float* orig  = (const float*)d_in[1];
    const float* nearv = (const float*)d_in[2];
    const float* farv  = (const float*)d_in[3];
    const float* enc   = (const float*)d_in[4];
    const int*   gidx  = (const int*)  d_in[5];
    float* out = (float*)d_out;

    const int N = in_sizes[2];  // near has one element per ray

    fused_kernel<<<NBLK, NTHR>>>(dirs, orig, nearv, farv, enc, gidx, out,
                                 N, (long long)out_size);
}

// round 17
// speedup vs baseline: 1.0343x; 1.0343x over previous
#include <cuda_runtime.h>
#include <cuda_bf16.h>

// LightplaneSplatter: splat N rays x 72 samples x 16 channels into a
// (1,128,128,128,16) grid with trilinear weights, masking OOB corners.
//
// R16: persistent kernel with in-kernel zero/splat overlap at 2 blocks/SM.
// R15 failed because 1 block/SM (18 warps) cannot saturate the LSU RED
// stream (L1 hit only 52.7% vs the 75% ceiling). Grid size is computed from
// the occupancy API (SMs x maxActiveBlocksPerSM), which both doubles the
// resident warps (36/SM) and makes the software global barrier deadlock-free
// by construction. Phases:
//   1: all blocks zero vertex planes z in [0, ZC+1)                (~4us)
//   2: blocks < nblk/5 zero planes [ZC+1,128)  (DRAM-bound)
//      remaining blocks splat cells bz <= ZC-1 (LSU-bound)         (overlap)
//   3: all blocks splat cells bz >= ZC                             (~74us)
//
// Inputs (metadata order):
//   d_in[0] directions  float32 [N,3]
//   d_in[1] origins     float32 [N,3]
//   d_in[2] near        float32 [N]
//   d_in[3] far         float32 [N]
//   d_in[4] encoding    float32 [N,16]
//   d_in[5] grid_idx    int32   [N]
// Output: float32 grid [1,128,128,128,16] flattened (33,554,432 elems).

#define GW 128
#define GH 128
#define GD 128
#define GC 16
#define NUM_SAMPLES 64
#define NUM_SAMPLES_INF 8
#define ST (NUM_SAMPLES + NUM_SAMPLES_INF)  // 72
#define DISPARITY_AT_INF 1e-4f

// Strides in floats
#define SXs (GC)            // 16
#define SYs (GW * GC)       // 2048
#define SZs (GH * GW * GC)  // 262144

#define NTHR 576   // 2 ray-slots x 72 samples x 4 channel-quads
#define ZC   20    // lo cells: bz <= ZC-1 (touch vertex planes z <= ZC)

__device__ int g_count = 0;
__device__ int g_gen   = 0;

__device__ __forceinline__ void gbar(int nblk) {
    __syncthreads();
    if (threadIdx.x == 0) {
        __threadfence();
        volatile int* vgen = &g_gen;
        const int gen = *vgen;
        if (atomicAdd(&g_count, 1) == nblk - 1) {
            g_count = 0;
            __threadfence();
            atomicExch(&g_gen, gen + 1);
        } else {
            while (*vgen == gen) { __nanosleep(64); }
        }
        __threadfence();
    }
    __syncthreads();
}

__device__ __forceinline__ void red_add_v4(float* p, float x, float y, float z, float w) {
    asm volatile("red.global.add.v4.f32 [%0], {%1, %2, %3, %4};"
                 :: "l"(p), "f"(x), "f"(y), "f"(z), "f"(w)
                 : "memory");
}

// Splat one (ray, sample, channel-quad); emits only cells with bz in [zlo, zhi].
__device__ __forceinline__ void splat_sample(
    int n, int si, int c4, int zlo, int zhi,
    const float* __restrict__ dirs, const float* __restrict__ orig,
    const float* __restrict__ nearv, const float* __restrict__ farv,
    const float* __restrict__ enc, const int* __restrict__ gidx,
    float* __restrict__ out)
{
    const float nr = nearv[n];
    const float fr = farv[n];

    float t;
    if (si < NUM_SAMPLES) {
        t = nr + (fr - nr) * (((float)si + 0.5f) * (1.0f / NUM_SAMPLES));
    } else {
        const float j    = (float)(si - NUM_SAMPLES + 1) * (1.0f / NUM_SAMPLES_INF);
        const float invf = 1.0f / fr;
        const float disp = invf + (DISPARITY_AT_INF - invf) * j;
        t = 1.0f / disp;
    }

    const float px = orig[n * 3 + 0] + t * dirs[n * 3 + 0];
    const float py = orig[n * 3 + 1] + t * dirs[n * 3 + 1];
    const float pz = orig[n * 3 + 2] + t * dirs[n * 3 + 2];

    const float vx = (px + 1.0f) * 0.5f * (float)(GW - 1);
    const float vy = (py + 1.0f) * 0.5f * (float)(GH - 1);
    const float vz = (pz + 1.0f) * 0.5f * (float)(GD - 1);

    const float bxf = floorf(vx);
    const float byf = floorf(vy);
    const float bzf = floorf(vz);

    // Written so NaN also fails -> skip.
    const bool maybe_in =
        (bxf >= -1.0f) && (bxf <= (float)(GW - 1)) &&
        (byf >= -1.0f) && (byf <= (float)(GH - 1)) &&
        (bzf >= -1.0f) && (bzf <= (float)(GD - 1));
    if (!maybe_in) return;

    const int bz = (int)bzf;
    if (bz < zlo || bz > zhi) return;   // other phase handles it

    const float fx = vx - bxf;
    const float fy = vy - byf;
    const float fz = vz - bzf;
    const int bx = (int)bxf;
    const int by = (int)byf;

    const float4 e = *reinterpret_cast<const float4*>(enc + n * GC + c4 * 4);
    const int   b = gidx[n];

    const float wx0 = 1.0f - fx, wx1 = fx;
    const float wy0 = 1.0f - fy, wy1 = fy;
    const float wz0 = 1.0f - fz, wz1 = fz;

    const bool x0 = (unsigned)bx       < GW;
    const bool x1 = (unsigned)(bx + 1) < GW;
    const bool y0 = (unsigned)by       < GH;
    const bool y1 = (unsigned)(by + 1) < GH;
    const bool z0 = (unsigned)bz       < GD;
    const bool z1 = (unsigned)(bz + 1) < GD;

    const long long basef =
        ((((long long)b * GD + bz) * GH + by) * GW + bx) * GC + c4 * 4;
    float* const pb = out + basef;

#pragma unroll
    for (int k = 0; k < 8; k++) {
        const int ddx = k & 1, ddy = (k >> 1) & 1, ddz = (k >> 2) & 1;
        const bool inb = (ddx ? x1 : x0) & (ddy ? y1 : y0) & (ddz ? z1 : z0);
        if (inb) {
            const float w = (ddx ? wx1 : wx0) * (ddy ? wy1 : wy0) * (ddz ? wz1 : wz0);
            red_add_v4(pb + (ddz * SZs + ddy * SYs + ddx * SXs),
                       w * e.x, w * e.y, w * e.z, w * e.w);
        }
    }
}

// Conservative per-ray test: can any sample's cell have bz in [zlo, zhi]?
// vz is monotone in t (up to rounding); slack 1.0 voxels absorbs fp noise.
__device__ __forceinline__ bool ray_touches_z(
    int n, int zlo, int zhi,
    const float* __restrict__ dirs, const float* __restrict__ orig,
    const float* __restrict__ nearv, const float* __restrict__ farv)
{
    const float dz_ = dirs[n * 3 + 2];
    const float oz_ = orig[n * 3 + 2];
    const float nr = nearv[n], fr = farv[n];
    const float t0 = nr + (fr - nr) * (0.5f / NUM_SAMPLES);
    const float t1 = 1.0f / DISPARITY_AT_INF;  // max sample depth
    const float va = (oz_ + t0 * dz_ + 1.0f) * 0.5f * (float)(GD - 1);
    const float vb = (oz_ + t1 * dz_ + 1.0f) * 0.5f * (float)(GD - 1);
    const float vmin = fminf(va, vb);
    const float vmax = fmaxf(va, vb);
    if (vmin > (float)(zhi + 1) + 1.0f) return false;  // all floors > zhi
    if (vmax < (float)zlo - 1.0f)       return false;  // all floors < zlo
    return true;
}

__global__ void __launch_bounds__(NTHR, 2) fused_kernel(
    const float* __restrict__ dirs,
    const float* __restrict__ orig,
    const float* __restrict__ nearv,
    const float* __restrict__ farv,
    const float* __restrict__ enc,
    const int*   __restrict__ gidx,
    float* __restrict__ out,
    int N, long long out_floats)
{
    const int tid  = threadIdx.x;
    const int bid  = blockIdx.x;
    const int nblk = gridDim.x;          // sized by occupancy: all co-resident

    float4* const out4 = (float4*)out;
    const float4 z4 = make_float4(0.f, 0.f, 0.f, 0.f);
    const long long lo4  = (long long)(ZC + 1) * SZs / 4;  // planes [0, ZC+1)
    const long long all4 = out_floats / 4;

    // thread -> (ray-slot, sample, channel-quad)
    const int rp  = tid / 288;          // 0 or 1
    const int rem = tid - rp * 288;
    const int si  = rem >> 2;           // 0..71
    const int c4  = rem & 3;            // 0..3

    // ---- phase 1: zero lo planes (all blocks) ----
    for (long long i = (long long)bid * NTHR + tid; i < lo4;
         i += (long long)nblk * NTHR)
        out4[i] = z4;
    gbar(nblk);

    // ---- phase 2: overlap hi zeroing with lo splat ----
    const int zb = nblk / 5;            // zeroing blocks (~30 SM-equivalents)
    if (bid < zb) {
        for (long long i = lo4 + (long long)bid * NTHR + tid; i < all4;
             i += (long long)zb * NTHR)
            out4[i] = z4;
    } else {
        const int nb = nblk - zb;
        for (int r = (bid - zb) * 2 + rp; r < N; r += nb * 2) {
            if (!ray_touches_z(r, -1, ZC - 1, dirs, orig, nearv, farv)) continue;
            splat_sample(r, si, c4, -1000000, ZC - 1,
                         dirs, orig, nearv, farv, enc, gidx, out);
        }
    }
    gbar(nblk);

    // ---- phase 3: splat hi cells (all blocks) ----
    for (int r = bid * 2 + rp; r < N; r += nblk * 2) {
        if (!ray_touches_z(r, ZC, GD - 1, dirs, orig, nearv, farv)) continue;
        splat_sample(r, si, c4, ZC, 1000000,
                     dirs, orig, nearv, farv, enc, gidx, out);
    }
}

extern "C" void kernel_launch(void* const* d_in, const int* in_sizes, int n_in,
                              void* d_out, int out_size)
{
    const float* dirs  = (const float*)d_in[0];
    const float* orig  = (const float*)d_in[1];
    const float* nearv = (const float*)d_in[2];
    const float* farv  = (const float*)d_in[3];
    const float* enc   = (const float*)d_in[4];
    const int*   gidx  = (const int*)  d_in[5];
    float* out = (float*)d_out;

    const int N = in_sizes[2];  // near has one element per ray

    // Deadlock-safe grid sizing: exactly the number of co-resident blocks.
    int dev = 0, sms = 148, perSM = 1;
    cudaGetDevice(&dev);
    cudaDeviceGetAttribute(&sms, cudaDevAttrMultiProcessorCount, dev);
    cudaOccupancyMaxActiveBlocksPerMultiprocessor(&perSM, fused_kernel, NTHR, 0);
    if (perSM < 1) perSM = 1;
    const int nblk = sms * perSM;

    fused_kernel<<<nblk, NTHR>>>(dirs, orig, nearv, farv, enc, gidx, out,
                                 N, (long long)out_size);
}